// round 16
// baseline (speedup 1.0000x reference)
#include <cuda_runtime.h>

// Problem constants (fixed by the reference)
#define NB   4
#define CC   128
#define HH   50
#define WW   50
#define RR   256
#define PHN  7
#define PWN  7
#define HW   (HH*WW)        // 2500
#define SCALE 0.0625f
#define CQ   (CC / 4)       // 32 channel quads
#define ROWQ (WW * CQ)      // 1600 float4 per spatial row

// fl(1/7) in f32 = 0x3E124925. XLA rewrites x/7 -> x * fl(1/7). Bit-exact match.
#define RECIP7 0x1.24924ap-3f

// NHWC scratch as float4 quads: 4*2500*32 float4 = 5.12 MB, 16B-aligned.
__device__ float4 g_featT4[NB * HW * CQ];

// ---------------------------------------------------------------------------
// Transpose NCHW -> NHWC, float4 output stores (round-14 winner, ~2.3us).
// grid: (79, 4)   block: (32, 8) = 256 threads
// ---------------------------------------------------------------------------
__global__ void __launch_bounds__(256)
nchw_to_nhwc(const float* __restrict__ feat) {
    __shared__ float4 t4[32][33];               // [spatial][quad], padded
    const int n  = blockIdx.y;
    const int s0 = blockIdx.x * 32;
    const float* src = feat + n * (CC * HW);
    float4* dst4 = g_featT4 + n * (HW * CQ);

    const int tx = threadIdx.x, ty = threadIdx.y;
    float* tf = (float*)t4;                     // element (s, c) at tf[s*132 + c]

    #pragma unroll
    for (int i = 0; i < 16; i++) {
        int c = ty + 8 * i;                     // warp-uniform channel
        int s = s0 + tx;
        float v = (s < HW) ? src[c * HW + s] : 0.f;
        tf[tx * 132 + c] = v;
    }
    __syncthreads();
    #pragma unroll
    for (int j = 0; j < 4; j++) {
        int sl = ty + 8 * j;
        int s  = s0 + sl;
        if (s < HW) dst4[s * CQ + tx] = t4[sl][tx];
    }
}

// ---------------------------------------------------------------------------
// RoI max-pool on NHWC, float4 channels, one warp per bin (round-10 loop),
// int32 addressing, incremental row pointers, DIRECT stores (no stage/barrier).
// grid: (7, 256); block: 224 = 7 warps; warp w owns pw=w; lane = channel quad.
// ---------------------------------------------------------------------------
__global__ void __launch_bounds__(224)
roipool_kernel(const float* __restrict__ rois, float* __restrict__ out) {
    const int r  = blockIdx.y;
    const int ph = blockIdx.x;
    const int pw = threadIdx.x >> 5;     // warp id == pw bin
    const int l  = threadIdx.x & 31;     // lane = channel quad

    const float* rp = rois + r * 5;
    const int b  = (int)rp[0];
    const int xs = (int)rintf(__fmul_rn(rp[1], SCALE));
    const int ys = (int)rintf(__fmul_rn(rp[2], SCALE));
    const int xe = (int)rintf(__fmul_rn(rp[3], SCALE));
    const int ye = (int)rintf(__fmul_rn(rp[4], SCALE));

    const float bin_h = __fmul_rn((float)max(ye - ys + 1, 1), RECIP7);
    const float bin_w = __fmul_rn((float)max(xe - xs + 1, 1), RECIP7);

    int hstart = (int)floorf(__fmul_rn((float)ph,       bin_h)) + ys;
    int hend   = (int)ceilf (__fmul_rn((float)(ph + 1), bin_h)) + ys;
    hstart = min(max(hstart, 0), HH);
    hend   = min(max(hend,   0), HH);

    int wstart = (int)floorf(__fmul_rn((float)pw,       bin_w)) + xs;
    int wend   = (int)ceilf (__fmul_rn((float)(pw + 1), bin_w)) + xs;
    wstart = min(max(wstart, 0), WW);
    wend   = min(max(wend,   0), WW);

    const int  cols = wend - wstart;
    const bool any  = (hend > hstart) && (cols > 0);

    // int32 offsets throughout (buffer is only 320k float4).
    const float4* p = g_featT4 + ((b * HW + hstart * WW + wstart) * CQ + l);

    const float NEG = -3.4e38f;
    float4 m0 = make_float4(NEG, NEG, NEG, NEG);
    float4 m1 = m0;

    // Dual accumulator chains over row pairs (round-10 proven loop).
    int rows = hend - hstart;
    for (; rows >= 2; rows -= 2) {
        const float4* ra = p;
        const float4* rb = p + ROWQ;
        #pragma unroll 4
        for (int x = 0; x < cols; x++) {
            float4 va = __ldg(ra); ra += CQ;
            float4 vb = __ldg(rb); rb += CQ;
            m0.x = fmaxf(m0.x, va.x); m0.y = fmaxf(m0.y, va.y);
            m0.z = fmaxf(m0.z, va.z); m0.w = fmaxf(m0.w, va.w);
            m1.x = fmaxf(m1.x, vb.x); m1.y = fmaxf(m1.y, vb.y);
            m1.z = fmaxf(m1.z, vb.z); m1.w = fmaxf(m1.w, vb.w);
        }
        p += 2 * ROWQ;
    }
    if (rows > 0) {                       // tail row
        const float4* ra = p;
        #pragma unroll 4
        for (int x = 0; x < cols; x++) {
            float4 va = __ldg(ra); ra += CQ;
            m0.x = fmaxf(m0.x, va.x); m0.y = fmaxf(m0.y, va.y);
            m0.z = fmaxf(m0.z, va.z); m0.w = fmaxf(m0.w, va.w);
        }
    }
    m0.x = fmaxf(m0.x, m1.x); m0.y = fmaxf(m0.y, m1.y);
    m0.z = fmaxf(m0.z, m1.z); m0.w = fmaxf(m0.w, m1.w);
    if (!any) m0 = make_float4(0.f, 0.f, 0.f, 0.f);

    // Direct store: out[r*6272 + c*49 + ph*7 + pw], c = 4l..4l+3.
    const int obase = r * (CC * PHN * PWN) + (4 * l) * (PHN * PWN) + ph * PWN + pw;
    out[obase]       = m0.x;
    out[obase + 49]  = m0.y;
    out[obase + 98]  = m0.z;
    out[obase + 147] = m0.w;
}

// ---------------------------------------------------------------------------
extern "C" void kernel_launch(void* const* d_in, const int* in_sizes, int n_in,
                              void* d_out, int out_size) {
    const float* feat = (const float*)d_in[0];   // (4,128,50,50)
    const float* rois = (const float*)d_in[1];   // (256,5)
    float* out = (float*)d_out;                  // (256,128,7,7)

    nchw_to_nhwc<<<dim3((HW + 31) / 32, NB), dim3(32, 8)>>>(feat);

    roipool_kernel<<<dim3(PHN, RR), 224>>>(rois, out);
}

// round 17
// speedup vs baseline: 1.2613x; 1.2613x over previous
#include <cuda_runtime.h>

// Problem constants (fixed by the reference)
#define NB   4
#define CC   128
#define HH   50
#define WW   50
#define RR   256
#define PHN  7
#define PWN  7
#define HW   (HH*WW)        // 2500
#define SCALE 0.0625f
#define CQ   (CC / 4)       // 32 channel quads
#define ROWQ (WW * CQ)      // 1600 float4 per spatial row

// fl(1/7) in f32 = 0x3E124925. XLA rewrites x/7 -> x * fl(1/7). Bit-exact match.
#define RECIP7 0x1.24924ap-3f

// NHWC scratch as float4 quads: 4*2500*32 float4 = 5.12 MB, 16B-aligned.
__device__ float4 g_featT4[NB * HW * CQ];

// ---------------------------------------------------------------------------
// Transpose NCHW -> NHWC, float4 output stores (round-14 winner, ~2.3us).
// grid: (79, 4)   block: (32, 8) = 256 threads
// ---------------------------------------------------------------------------
__global__ void __launch_bounds__(256)
nchw_to_nhwc(const float* __restrict__ feat) {
    __shared__ float4 t4[32][33];               // [spatial][quad], padded
    const int n  = blockIdx.y;
    const int s0 = blockIdx.x * 32;
    const float* src = feat + n * (CC * HW);
    float4* dst4 = g_featT4 + n * (HW * CQ);

    const int tx = threadIdx.x, ty = threadIdx.y;
    float* tf = (float*)t4;                     // element (s, c) at tf[s*132 + c]

    #pragma unroll
    for (int i = 0; i < 16; i++) {
        int c = ty + 8 * i;                     // warp-uniform channel
        int s = s0 + tx;
        float v = (s < HW) ? src[c * HW + s] : 0.f;
        tf[tx * 132 + c] = v;
    }
    __syncthreads();
    #pragma unroll
    for (int j = 0; j < 4; j++) {
        int sl = ty + 8 * j;
        int s  = s0 + sl;
        if (s < HW) dst4[s * CQ + tx] = t4[sl][tx];
    }
}

// ---------------------------------------------------------------------------
// RoI max-pool on NHWC, float4 channels, one warp per bin.
// int32 addressing + incremental row pointers (round-16, 32 regs) combined
// with the staged shared epilogue (round-15, coalesced-ish stores).
// grid: (7, 256); block: 224 = 7 warps; warp w owns pw=w; lane = channel quad.
// ---------------------------------------------------------------------------
__global__ void __launch_bounds__(224)
roipool_kernel(const float* __restrict__ rois, float* __restrict__ out) {
    __shared__ float4 stage4[PWN][33];   // [pw][lane], padded

    const int r  = blockIdx.y;
    const int ph = blockIdx.x;
    const int pw = threadIdx.x >> 5;     // warp id == pw bin
    const int l  = threadIdx.x & 31;     // lane = channel quad

    const float* rp = rois + r * 5;
    const int b  = (int)rp[0];
    const int xs = (int)rintf(__fmul_rn(rp[1], SCALE));
    const int ys = (int)rintf(__fmul_rn(rp[2], SCALE));
    const int xe = (int)rintf(__fmul_rn(rp[3], SCALE));
    const int ye = (int)rintf(__fmul_rn(rp[4], SCALE));

    const float bin_h = __fmul_rn((float)max(ye - ys + 1, 1), RECIP7);
    const float bin_w = __fmul_rn((float)max(xe - xs + 1, 1), RECIP7);

    int hstart = (int)floorf(__fmul_rn((float)ph,       bin_h)) + ys;
    int hend   = (int)ceilf (__fmul_rn((float)(ph + 1), bin_h)) + ys;
    hstart = min(max(hstart, 0), HH);
    hend   = min(max(hend,   0), HH);

    int wstart = (int)floorf(__fmul_rn((float)pw,       bin_w)) + xs;
    int wend   = (int)ceilf (__fmul_rn((float)(pw + 1), bin_w)) + xs;
    wstart = min(max(wstart, 0), WW);
    wend   = min(max(wend,   0), WW);

    const int  cols = wend - wstart;
    const bool any  = (hend > hstart) && (cols > 0);

    // int32 offsets throughout (buffer is only 320k float4).
    const float4* p = g_featT4 + ((b * HW + hstart * WW + wstart) * CQ + l);

    const float NEG = -3.4e38f;
    float4 m0 = make_float4(NEG, NEG, NEG, NEG);
    float4 m1 = m0;

    // Dual accumulator chains over row pairs (round-10 proven loop).
    int rows = hend - hstart;
    for (; rows >= 2; rows -= 2) {
        const float4* ra = p;
        const float4* rb = p + ROWQ;
        #pragma unroll 4
        for (int x = 0; x < cols; x++) {
            float4 va = __ldg(ra); ra += CQ;
            float4 vb = __ldg(rb); rb += CQ;
            m0.x = fmaxf(m0.x, va.x); m0.y = fmaxf(m0.y, va.y);
            m0.z = fmaxf(m0.z, va.z); m0.w = fmaxf(m0.w, va.w);
            m1.x = fmaxf(m1.x, vb.x); m1.y = fmaxf(m1.y, vb.y);
            m1.z = fmaxf(m1.z, vb.z); m1.w = fmaxf(m1.w, vb.w);
        }
        p += 2 * ROWQ;
    }
    if (rows > 0) {                       // tail row
        const float4* ra = p;
        #pragma unroll 4
        for (int x = 0; x < cols; x++) {
            float4 va = __ldg(ra); ra += CQ;
            m0.x = fmaxf(m0.x, va.x); m0.y = fmaxf(m0.y, va.y);
            m0.z = fmaxf(m0.z, va.z); m0.w = fmaxf(m0.w, va.w);
        }
    }
    m0.x = fmaxf(m0.x, m1.x); m0.y = fmaxf(m0.y, m1.y);
    m0.z = fmaxf(m0.z, m1.z); m0.w = fmaxf(m0.w, m1.w);
    if (!any) m0 = make_float4(0.f, 0.f, 0.f, 0.f);
    stage4[pw][l] = m0;
    __syncthreads();

    // Cooperative write of the 128x7 tile: out[(r*128+c)*49 + ph*7 + pw]
    const float* sf = (const float*)stage4;   // channel c of bin pw: pw*132 + c
    float* ob = out + r * (CC * PHN * PWN) + ph * PWN;
    #pragma unroll
    for (int e = threadIdx.x; e < CC * PWN; e += 224) {
        int c   = e / PWN;
        int pww = e - c * PWN;
        ob[c * (PHN * PWN) + pww] = sf[pww * 132 + c];
    }
}

// ---------------------------------------------------------------------------
extern "C" void kernel_launch(void* const* d_in, const int* in_sizes, int n_in,
                              void* d_out, int out_size) {
    const float* feat = (const float*)d_in[0];   // (4,128,50,50)
    const float* rois = (const float*)d_in[1];   // (256,5)
    float* out = (float*)d_out;                  // (256,128,7,7)

    nchw_to_nhwc<<<dim3((HW + 31) / 32, NB), dim3(32, 8)>>>(feat);

    roipool_kernel<<<dim3(PHN, RR), 224>>>(rois, out);
}